// round 13
// baseline (speedup 1.0000x reference)
#include <cuda_runtime.h>
#include <cstdint>

// RadianceFieldTT — R12: R11 with the pass kernels' register cap lifted.
//   __launch_bounds__(TILE, 3) capped regs at 170 -> ptxas spilled the
//   128-register weight array -> inner loop re-read weights from local
//   memory every sample. (TILE, 2) caps at 256: weights stay in registers.
//
//  Chain: v0 = core0[d0]
//         pass A: v3 = v0 @ T_A[d1,d2,d3], written at g_vA[rankB[sid]]
//         pass B: v6 = v3 @ T_B[d4,d5,d6], gather SEQUENTIAL, scatter by sid
//         epi   : out = v6 @ (W7(d7) @ (payload @ SH(b)))

#define NMAX  (1024 * 256)
#define RANK  64
#define TILE  128
#define VS    68          // smem v row stride in floats (272 B: 16B-aligned)

typedef unsigned long long u64;

__device__ float    g_vA[(size_t)NMAX * 64];
__device__ float    g_vB[(size_t)NMAX * 64];
__device__ float    g_w2[1024 * 4096];     // packed triple weights (16 MB)
__device__ float    g_pair[128 * 4096];    // temp pair products (2 MB)
__device__ int      g_perm[2][NMAX];
__device__ int      g_rankB[NMAX];         // position of sample in perm B
__device__ unsigned g_dig[NMAX];
__device__ int      g_cnt[1024];
__device__ int      g_cur[1024];

__device__ __forceinline__ u64 pk2(float lo, float hi) {
    u64 r; asm("mov.b64 %0, {%1, %2};" : "=l"(r) : "f"(lo), "f"(hi)); return r;
}
__device__ __forceinline__ void upk2(u64 v, float& lo, float& hi) {
    asm("mov.b64 {%0, %1}, %2;" : "=f"(lo), "=f"(hi) : "l"(v));
}
__device__ __forceinline__ u64 ffma2(u64 a, u64 b, u64 c) {
    u64 d; asm("fma.rn.f32x2 %0, %1, %2, %3;" : "=l"(d) : "l"(a), "l"(b), "l"(c)); return d;
}
__device__ __forceinline__ u64 add2(u64 a, u64 b) {
    u64 d; asm("add.rn.f32x2 %0, %1, %2;" : "=l"(d) : "l"(a), "l"(b)); return d;
}

__device__ __forceinline__ unsigned compute_dig(float cx, float cy, float cz) {
    const int ix = min(255, max(0, (int)floorf((cx * 0.5f + 0.5f) * 256.f)));
    const int iy = min(255, max(0, (int)floorf((cy * 0.5f + 0.5f) * 256.f)));
    const int iz = min(255, max(0, (int)floorf((cz * 0.5f + 0.5f) * 256.f)));
    unsigned dig = 0;
#pragma unroll
    for (int l = 0; l < 8; ++l) {
        const int s = 7 - l;
        const unsigned d = (((ix >> s) & 1) << 2) | (((iy >> s) & 1) << 1) | ((iz >> s) & 1);
        dig |= d << (4 * l);
    }
    return dig;
}
// key for pass p (0/1): digits (3p+1, 3p+2, 3p+3) -> 0..511
__device__ __forceinline__ int trip_key(unsigned dg, int p) {
    const int l0 = 3 * p + 1;
    return (int)(((dg >> (4 * l0)) & 7u) * 64u + ((dg >> (4 * (l0 + 1))) & 7u) * 8u
                 + ((dg >> (4 * (l0 + 2))) & 7u));
}

// ---------------- sort pipeline ----------------
__global__ void k_zero() {
    const int t = blockIdx.x * 256 + threadIdx.x;
    if (t < 1024) g_cnt[t] = 0;
}

__global__ __launch_bounds__(256) void k_keys(const float* __restrict__ coords) {
    __shared__ int lc[1024];
    const int t = threadIdx.x;
#pragma unroll
    for (int i = 0; i < 4; ++i) lc[t + 256 * i] = 0;
    __syncthreads();
    const int n = blockIdx.x * 256 + t;
    const unsigned dg = compute_dig(coords[3 * n], coords[3 * n + 1], coords[3 * n + 2]);
    g_dig[n] = dg;
#pragma unroll
    for (int p = 0; p < 2; ++p) atomicAdd(&lc[p * 512 + trip_key(dg, p)], 1);
    __syncthreads();
#pragma unroll
    for (int i = 0; i < 4; ++i) {
        const int j = t + 256 * i;
        if (lc[j]) atomicAdd(&g_cnt[j], lc[j]);
    }
}

// parallel segmented exclusive scan: 1 block, 1024 threads, 2 segments of 512
__global__ __launch_bounds__(1024) void k_scan() {
    __shared__ int s[1024];
    const int t = threadIdx.x;
    const int v = g_cnt[t];
    s[t] = v;
    __syncthreads();
#pragma unroll
    for (int off = 1; off < 512; off <<= 1) {
        const int x = ((t & 511) >= off) ? s[t - off] : 0;
        __syncthreads();
        s[t] += x;
        __syncthreads();
    }
    g_cur[t] = s[t] - v;   // exclusive within segment
}

__global__ __launch_bounds__(256) void k_scatter() {
    __shared__ int lc[1024], lb[1024], lp[1024];
    const int t = threadIdx.x;
#pragma unroll
    for (int i = 0; i < 4; ++i) { lc[t + 256 * i] = 0; lp[t + 256 * i] = 0; }
    __syncthreads();
    const int n = blockIdx.x * 256 + t;
    const unsigned dg = g_dig[n];
    int key[2];
#pragma unroll
    for (int p = 0; p < 2; ++p) {
        key[p] = p * 512 + trip_key(dg, p);
        atomicAdd(&lc[key[p]], 1);
    }
    __syncthreads();
#pragma unroll
    for (int i = 0; i < 4; ++i) {
        const int j = t + 256 * i;
        if (lc[j]) lb[j] = atomicAdd(&g_cur[j], lc[j]);
    }
    __syncthreads();
#pragma unroll
    for (int p = 0; p < 2; ++p) {
        const int r = atomicAdd(&lp[key[p]], 1);
        const int pos = lb[key[p]] + r;
        g_perm[p][pos] = n;
        if (p == 1) g_rankB[n] = pos;
    }
}

// ---------------- precombine step 1: pairs ----------------
// g_pair[pc][r][s] = sum_k cores[3p][r][da][k] * cores[3p+1][k][db][s]
__global__ void __launch_bounds__(128) k_pair(const float* __restrict__ cores)
{
    __shared__ float sA[4096];
    __shared__ float sB[4096];
    const int pc = blockIdx.x;             // 0..127: p*64 + da*8 + db
    const int p  = pc >> 6;
    const int da = (pc >> 3) & 7;
    const int db = pc & 7;
    const int t = threadIdx.x;

    const float* A  = cores + (size_t)(3 * p) * 32768 + da * 64;
    const float* Bm = cores + (size_t)(3 * p + 1) * 32768 + db * 64;
    for (int i = t; i < 1024; i += 128) {
        const int row = i >> 4, c4 = (i & 15) * 4;
        *(float4*)(sA + row * 64 + c4) = *(const float4*)(A  + row * 512 + c4);
        *(float4*)(sB + row * 64 + c4) = *(const float4*)(Bm + row * 512 + c4);
    }
    __syncthreads();

    const int r  = t >> 1;
    const int s0 = (t & 1) * 32;
    float acc[32];
#pragma unroll
    for (int i = 0; i < 32; ++i) acc[i] = 0.f;
#pragma unroll 4
    for (int k = 0; k < 64; ++k) {
        const float a = sA[r * 64 + k];
#pragma unroll
        for (int i = 0; i < 32; ++i) acc[i] = fmaf(a, sB[k * 64 + s0 + i], acc[i]);
    }
    float* dst = g_pair + (size_t)pc * 4096 + r * 64 + s0;
#pragma unroll
    for (int i = 0; i < 32; ++i) dst[i] = acc[i];
}

// ---------------- precombine step 2: triples (packed output) ----------------
// T[tc] = g_pair[p*64+da*8+db] @ cores[3p+2](dc),  tc = p*512 + da*64 + db*8 + dc
// Packed: float idx ((tc*32 + (r>>1))*32 + (s>>1))*4 + (s&1)*2 + (r&1)
__global__ void __launch_bounds__(256) k_triple(const float* __restrict__ cores)
{
    __shared__ float sA[4096];
    __shared__ float sB[4096];
    const int tc = blockIdx.x;             // 0..1023
    const int p  = tc >> 9;
    const int da = (tc >> 6) & 7;
    const int db = (tc >> 3) & 7;
    const int dc = tc & 7;
    const int t = threadIdx.x;

    const float* A  = g_pair + (size_t)(p * 64 + da * 8 + db) * 4096;   // row-major 64x64
    const float* Bm = cores + (size_t)(3 * p + 2) * 32768 + dc * 64;
    for (int i = t; i < 1024; i += 256) {
        const int row = i >> 4, c4 = (i & 15) * 4;
        *(float4*)(sA + row * 64 + c4) = *(const float4*)(A  + row * 64 + c4);
        *(float4*)(sB + row * 64 + c4) = *(const float4*)(Bm + row * 512 + c4);
    }
    __syncthreads();

    const int r  = t >> 2;                 // 0..63
    const int s0 = (t & 3) * 16;
    float acc[16];
#pragma unroll
    for (int i = 0; i < 16; ++i) acc[i] = 0.f;
#pragma unroll 4
    for (int k = 0; k < 64; ++k) {
        const float a = sA[r * 64 + k];
#pragma unroll
        for (int i = 0; i < 16; ++i) acc[i] = fmaf(a, sB[k * 64 + s0 + i], acc[i]);
    }
    const int q = r >> 1, pr = r & 1;
#pragma unroll
    for (int i = 0; i < 16; ++i) {
        const int j = s0 + i;
        g_w2[((size_t)(tc * 32 + q) * 32 + (j >> 1)) * 4 + (j & 1) * 2 + pr] = acc[i];
    }
}

// ---------------- pass A: core0 -> g_vA[rankB] ----------------
__global__ __launch_bounds__(TILE, 2) void k_passA(const float* __restrict__ core0)
{
    __shared__ float vt[TILE * VS];
    __shared__ int   opos[TILE];
    __shared__ int   keys[TILE];
    const int t = threadIdx.x, lane = t & 31, w = t >> 5;
    const int base = blockIdx.x * TILE;

    {
        const int sid = g_perm[0][base + t];
        const unsigned dg = g_dig[sid];
        keys[t] = trip_key(dg, 0);
        opos[t] = g_rankB[sid];
        // v0 = core0[d0]: 8 distinct rows, L1-resident; thread fills own row
        const float4* src = (const float4*)(core0 + (dg & 7u) * RANK);
        float* drow = vt + t * VS;
#pragma unroll
        for (int j = 0; j < 16; ++j) *(float4*)(drow + 4 * j) = src[j];
    }
    __syncthreads();

    u64 wa[32], wb[32];
    int cur = -1;
#pragma unroll 1
    for (int s = w * 32; s < w * 32 + 32; ++s) {
        const int key = keys[s];
        if (key != cur) {
            cur = key;
            const ulonglong2* wp = (const ulonglong2*)g_w2 + (size_t)key * 1024 + lane;
#pragma unroll
            for (int k = 0; k < 32; ++k) {
                const ulonglong2 z = wp[k * 32];   // coalesced LDG.128
                wa[k] = z.x; wb[k] = z.y;
            }
        }
        const ulonglong2* vr = (const ulonglong2*)(vt + s * VS);
        u64 a0 = 0ull, a1 = 0ull, b0 = 0ull, b1 = 0ull;
#pragma unroll
        for (int q = 0; q < 16; ++q) {
            const ulonglong2 p = vr[q];            // uniform LDS.128 (broadcast)
            a0 = ffma2(wa[2 * q + 0], p.x, a0);
            b0 = ffma2(wb[2 * q + 0], p.x, b0);
            a1 = ffma2(wa[2 * q + 1], p.y, a1);
            b1 = ffma2(wb[2 * q + 1], p.y, b1);
        }
        float x0, x1, y0, y1;
        upk2(add2(a0, a1), x0, x1);
        upk2(add2(b0, b1), y0, y1);
        *(u64*)(g_vA + (size_t)opos[s] * 64 + 2 * lane) = pk2(x0 + x1, y0 + y1);
    }
}

// ---------------- pass B: g_vA (sequential) -> g_vB[sid] ----------------
__global__ __launch_bounds__(TILE, 2) void k_passB()
{
    __shared__ float vt[TILE * VS];
    __shared__ int   sids[TILE];
    __shared__ int   keys[TILE];
    const int t = threadIdx.x, lane = t & 31, w = t >> 5;
    const int base = blockIdx.x * TILE;

    {
        const int sid = g_perm[1][base + t];
        sids[t] = sid;
        keys[t] = trip_key(g_dig[sid], 1);
    }
    // sequential coalesced gather: row r of tile lives at g_vA[base + r]
    {
        const int h = t & 1;
#pragma unroll
        for (int r = t >> 1; r < TILE; r += 64) {
            const float* srow = g_vA + (size_t)(base + r) * 64;
            float* drow = vt + r * VS;
#pragma unroll
            for (int j = 0; j < 8; ++j) {
                const int c = 2 * j + h;
                *(float4*)(drow + c * 4) = *(const float4*)(srow + c * 4);
            }
        }
    }
    __syncthreads();

    u64 wa[32], wb[32];
    int cur = -1;
#pragma unroll 1
    for (int s = w * 32; s < w * 32 + 32; ++s) {
        const int key = keys[s];
        if (key != cur) {
            cur = key;
            const ulonglong2* wp = (const ulonglong2*)g_w2 + (size_t)(512 + key) * 1024 + lane;
#pragma unroll
            for (int k = 0; k < 32; ++k) {
                const ulonglong2 z = wp[k * 32];
                wa[k] = z.x; wb[k] = z.y;
            }
        }
        const ulonglong2* vr = (const ulonglong2*)(vt + s * VS);
        u64 a0 = 0ull, a1 = 0ull, b0 = 0ull, b1 = 0ull;
#pragma unroll
        for (int q = 0; q < 16; ++q) {
            const ulonglong2 p = vr[q];
            a0 = ffma2(wa[2 * q + 0], p.x, a0);
            b0 = ffma2(wb[2 * q + 0], p.x, b0);
            a1 = ffma2(wa[2 * q + 1], p.y, a1);
            b1 = ffma2(wb[2 * q + 1], p.y, b1);
        }
        float x0, x1, y0, y1;
        upk2(add2(a0, a1), x0, x1);
        upk2(add2(b0, b1), y0, y1);
        *(u64*)(g_vB + (size_t)sids[s] * 64 + 2 * lane) = pk2(x0 + x1, y0 + y1);
    }
}

// ---------------- epilogue: fold W7(d7) @ (payload @ SH) ----------------
__global__ __launch_bounds__(256) void k_epi(const float* __restrict__ coords,
                                             const float* __restrict__ viewdirs,
                                             const float* __restrict__ cores,
                                             const float* __restrict__ payload,
                                             float* __restrict__ out, int N)
{
    __shared__ float pp[256];        // P' : 64 x float4
    __shared__ float wps[8 * 260];   // WP[d][r][j]: d*260 + r*4 + j
    const int tid = threadIdx.x;
    const int b   = blockIdx.x;
    const int n   = b * 256 + tid;

    const float cx = coords[3 * n + 0];
    const float cy = coords[3 * n + 1];
    const float cz = coords[3 * n + 2];
    const float msk = (fabsf(cx) <= 1.f && fabsf(cy) <= 1.f && fabsf(cz) <= 1.f) ? 1.f : 0.f;
    const int d7 = (int)((g_dig[n] >> 28) & 7u);

    if (tid < RANK) {
        const float* vd = viewdirs + 3 * b;
        const float dx = vd[0], dy = vd[1], dz = vd[2];
        float shv[9];
        shv[0] = 0.28209479177387814f;
        shv[1] = -0.4886025119029199f * dy;
        shv[2] =  0.4886025119029199f * dz;
        shv[3] = -0.4886025119029199f * dx;
        shv[4] =  1.0925484305920792f * dx * dy;
        shv[5] = -1.0925484305920792f * dy * dz;
        shv[6] =  0.31539156525252005f * (2.f * dz * dz - dx * dx - dy * dy);
        shv[7] = -1.0925484305920792f * dx * dz;
        shv[8] =  0.5462742152960396f * (dx * dx - dy * dy);
        const float* pr = payload + tid * 28;
        float s0 = 0.f, s1 = 0.f, s2 = 0.f;
#pragma unroll
        for (int j = 0; j < 9; ++j) {
            s0 = fmaf(pr[j],      shv[j], s0);
            s1 = fmaf(pr[9 + j],  shv[j], s1);
            s2 = fmaf(pr[18 + j], shv[j], s2);
        }
        *(float4*)(pp + 4 * tid) = make_float4(s0, s1, s2, pr[27]);
    }
    __syncthreads();

    // WP[d] = W7(d) @ P'
#pragma unroll
    for (int i = 0; i < 2; ++i) {
        const int idx = tid + i * 256;
        const int d = idx >> 6, r = idx & 63;
        const float* src = cores + (size_t)6 * 32768 + r * 512 + d * 64;
        float a0 = 0.f, a1 = 0.f, a2 = 0.f, a3 = 0.f;
#pragma unroll 4
        for (int s4 = 0; s4 < 16; ++s4) {
            const float4 w4 = *(const float4*)(src + 4 * s4);
            const float4 p0 = *(const float4*)(pp + 4 * (4 * s4 + 0));
            const float4 p1 = *(const float4*)(pp + 4 * (4 * s4 + 1));
            const float4 p2 = *(const float4*)(pp + 4 * (4 * s4 + 2));
            const float4 p3 = *(const float4*)(pp + 4 * (4 * s4 + 3));
            a0 = fmaf(w4.x, p0.x, a0); a1 = fmaf(w4.x, p0.y, a1);
            a2 = fmaf(w4.x, p0.z, a2); a3 = fmaf(w4.x, p0.w, a3);
            a0 = fmaf(w4.y, p1.x, a0); a1 = fmaf(w4.y, p1.y, a1);
            a2 = fmaf(w4.y, p1.z, a2); a3 = fmaf(w4.y, p1.w, a3);
            a0 = fmaf(w4.z, p2.x, a0); a1 = fmaf(w4.z, p2.y, a1);
            a2 = fmaf(w4.z, p2.z, a2); a3 = fmaf(w4.z, p2.w, a3);
            a0 = fmaf(w4.w, p3.x, a0); a1 = fmaf(w4.w, p3.y, a1);
            a2 = fmaf(w4.w, p3.z, a2); a3 = fmaf(w4.w, p3.w, a3);
        }
        *(float4*)(wps + d * 260 + r * 4) = make_float4(a0, a1, a2, a3);
    }
    __syncthreads();

    // out = v6 @ WP[d7]  (v6 rows in g_vB, natural order -> coalesced)
    float o0 = 0.f, o1 = 0.f, o2 = 0.f, o3 = 0.f;
    {
        const float* vrowg = g_vB + (size_t)n * 64;
        const float* wrow = wps + d7 * 260;
#pragma unroll
        for (int q = 0; q < 16; ++q) {
            const float4 t = *(const float4*)(vrowg + 4 * q);
            const float4 p0 = *(const float4*)(wrow + 4 * (4 * q + 0));
            const float4 p1 = *(const float4*)(wrow + 4 * (4 * q + 1));
            const float4 p2 = *(const float4*)(wrow + 4 * (4 * q + 2));
            const float4 p3 = *(const float4*)(wrow + 4 * (4 * q + 3));
            o0 = fmaf(t.x, p0.x, o0); o1 = fmaf(t.x, p0.y, o1);
            o2 = fmaf(t.x, p0.z, o2); o3 = fmaf(t.x, p0.w, o3);
            o0 = fmaf(t.y, p1.x, o0); o1 = fmaf(t.y, p1.y, o1);
            o2 = fmaf(t.y, p1.z, o2); o3 = fmaf(t.y, p1.w, o3);
            o0 = fmaf(t.z, p2.x, o0); o1 = fmaf(t.z, p2.y, o1);
            o2 = fmaf(t.z, p2.z, o2); o3 = fmaf(t.z, p2.w, o3);
            o0 = fmaf(t.w, p3.x, o0); o1 = fmaf(t.w, p3.y, o1);
            o2 = fmaf(t.w, p3.z, o2); o3 = fmaf(t.w, p3.w, o3);
        }
    }
    out[3 * n + 0] = o0 * msk;
    out[3 * n + 1] = o1 * msk;
    out[3 * n + 2] = o2 * msk;
    out[3 * N + n] = o3 * msk;   // sigma block after rgb block
}

extern "C" void kernel_launch(void* const* d_in, const int* in_sizes, int n_in,
                              void* d_out, int out_size) {
    const float* coords   = (const float*)d_in[0];  // (B,R,3)
    const float* viewdirs = (const float*)d_in[1];  // (B,3)
    const float* core0    = (const float*)d_in[2];  // (1,8,64)
    const float* cores    = (const float*)d_in[3];  // (7,64,8,64)
    const float* payload  = (const float*)d_in[4];  // (64,28)

    const int N = in_sizes[0] / 3;   // 262144
    const int B = in_sizes[1] / 3;   // 1024

    k_zero<<<4, 256>>>();
    k_keys<<<N / 256, 256>>>(coords);
    k_pair<<<128, 128>>>(cores);
    k_scan<<<1, 1024>>>();
    k_triple<<<1024, 256>>>(cores);
    k_scatter<<<N / 256, 256>>>();
    k_passA<<<N / TILE, TILE>>>(core0);
    k_passB<<<N / TILE, TILE>>>();
    k_epi<<<B, 256>>>(coords, viewdirs, cores, payload, (float*)d_out, N);
}

// round 14
// speedup vs baseline: 1.0774x; 1.0774x over previous
#include <cuda_runtime.h>
#include <cstdint>

// RadianceFieldTT — R13: back to the measured-best R9 architecture
// (3 streaming passes, 64 buckets/pass, 3 MB pair-table) with two fixes:
//   (a) parallel segmented scan (R9's serial scan measured 29 us; parallel 4.8)
//   (b) chained permutation placement: pass p writes rows in pass p+1's
//       permutation order -> passes 1,2 gather SEQUENTIALLY (coalesced);
//       only the scatter side stays random.
//
//  Chain: v0 = core0[d0]
//         pass0: v2 = v0 @ C0[d1,d2]   -> g_vA[rank1[sid]]
//         pass1: v4 = v2 @ C1[d3,d4]   -> g_vB[rank2[sid]]   (gather seq)
//         pass2: v6 = v4 @ C2[d5,d6]   -> g_vA[sid]          (gather seq)
//         epi  : out = v6 @ (W7(d7) @ (payload @ SH(b)))

#define NMAX  (1024 * 256)
#define RANK  64
#define TILE  128
#define VS    68          // smem v row stride in floats (272 B: 16B-aligned)

typedef unsigned long long u64;

__device__ float    g_vA[(size_t)NMAX * 64];
__device__ float    g_vB[(size_t)NMAX * 64];
__device__ float    g_w2[192 * 4096];      // packed pair weights (3 MB)
__device__ int      g_perm[3][NMAX];
__device__ int      g_rk1[NMAX];           // position of sample in perm 1
__device__ int      g_rk2[NMAX];           // position of sample in perm 2
__device__ unsigned g_dig[NMAX];
__device__ int      g_cnt[192];
__device__ int      g_cur[192];

__device__ __forceinline__ u64 pk2(float lo, float hi) {
    u64 r; asm("mov.b64 %0, {%1, %2};" : "=l"(r) : "f"(lo), "f"(hi)); return r;
}
__device__ __forceinline__ void upk2(u64 v, float& lo, float& hi) {
    asm("mov.b64 {%0, %1}, %2;" : "=f"(lo), "=f"(hi) : "l"(v));
}
__device__ __forceinline__ u64 ffma2(u64 a, u64 b, u64 c) {
    u64 d; asm("fma.rn.f32x2 %0, %1, %2, %3;" : "=l"(d) : "l"(a), "l"(b), "l"(c)); return d;
}
__device__ __forceinline__ u64 add2(u64 a, u64 b) {
    u64 d; asm("add.rn.f32x2 %0, %1, %2;" : "=l"(d) : "l"(a), "l"(b)); return d;
}

__device__ __forceinline__ unsigned compute_dig(float cx, float cy, float cz) {
    const int ix = min(255, max(0, (int)floorf((cx * 0.5f + 0.5f) * 256.f)));
    const int iy = min(255, max(0, (int)floorf((cy * 0.5f + 0.5f) * 256.f)));
    const int iz = min(255, max(0, (int)floorf((cz * 0.5f + 0.5f) * 256.f)));
    unsigned dig = 0;
#pragma unroll
    for (int l = 0; l < 8; ++l) {
        const int s = 7 - l;
        const unsigned d = (((ix >> s) & 1) << 2) | (((iy >> s) & 1) << 1) | ((iz >> s) & 1);
        dig |= d << (4 * l);
    }
    return dig;
}
// key for pass p (0,1,2): digits (2p+1, 2p+2) -> 0..63
__device__ __forceinline__ int pair_key(unsigned dg, int p) {
    return (int)(((dg >> (4 * (2 * p + 1))) & 7u) * 8u + ((dg >> (4 * (2 * p + 2))) & 7u));
}

// ---------------- sort pipeline ----------------
__global__ void k_zero() { if (threadIdx.x < 192) g_cnt[threadIdx.x] = 0; }

__global__ __launch_bounds__(256) void k_keys(const float* __restrict__ coords) {
    __shared__ int lc[192];
    const int t = threadIdx.x;
    if (t < 192) lc[t] = 0;
    __syncthreads();
    const int n = blockIdx.x * 256 + t;
    const unsigned dg = compute_dig(coords[3 * n], coords[3 * n + 1], coords[3 * n + 2]);
    g_dig[n] = dg;
#pragma unroll
    for (int p = 0; p < 3; ++p) atomicAdd(&lc[p * 64 + pair_key(dg, p)], 1);
    __syncthreads();
    if (t < 192 && lc[t]) atomicAdd(&g_cnt[t], lc[t]);
}

// parallel segmented exclusive scan: 1 block, 192 threads, 3 segments of 64
__global__ __launch_bounds__(192) void k_scan() {
    __shared__ int s[192];
    const int t = threadIdx.x;
    const int v = g_cnt[t];
    s[t] = v;
    __syncthreads();
#pragma unroll
    for (int off = 1; off < 64; off <<= 1) {
        const int x = ((t & 63) >= off) ? s[t - off] : 0;
        __syncthreads();
        s[t] += x;
        __syncthreads();
    }
    g_cur[t] = s[t] - v;   // exclusive within segment
}

__global__ __launch_bounds__(256) void k_scatter() {
    __shared__ int lc[192], lb[192], lp[192];
    const int t = threadIdx.x;
    if (t < 192) { lc[t] = 0; lp[t] = 0; }
    __syncthreads();
    const int n = blockIdx.x * 256 + t;
    const unsigned dg = g_dig[n];
    int key[3];
#pragma unroll
    for (int p = 0; p < 3; ++p) {
        key[p] = p * 64 + pair_key(dg, p);
        atomicAdd(&lc[key[p]], 1);
    }
    __syncthreads();
    if (t < 192 && lc[t]) lb[t] = atomicAdd(&g_cur[t], lc[t]);
    __syncthreads();
#pragma unroll
    for (int p = 0; p < 3; ++p) {
        const int r = atomicAdd(&lp[key[p]], 1);
        const int pos = lb[key[p]] + r;
        g_perm[p][pos] = n;
        if (p == 1) g_rk1[n] = pos;
        if (p == 2) g_rk2[n] = pos;
    }
}

// ---------------- precombine: packed pair-level weights ----------------
// C[r][s] = sum_k cores[2p][r][da][k] * cores[2p+1][k][db][s]
// Packed: float idx ((combo*32 + (r>>1))*32 + (s>>1))*4 + (s&1)*2 + (r&1)
__global__ void __launch_bounds__(128) precombine_kernel(const float* __restrict__ cores)
{
    __shared__ float sA[4096];
    __shared__ float sB[4096];
    const int combo = blockIdx.x;          // 0..191: p*64 + da*8 + db
    const int p  = combo >> 6;
    const int da = (combo >> 3) & 7;
    const int db = combo & 7;
    const int t = threadIdx.x;

    const float* A  = cores + (size_t)(2 * p) * 32768 + da * 64;
    const float* Bm = cores + (size_t)(2 * p + 1) * 32768 + db * 64;
    for (int i = t; i < 1024; i += 128) {
        const int row = i >> 4, c4 = (i & 15) * 4;
        *(float4*)(sA + row * 64 + c4) = *(const float4*)(A  + row * 512 + c4);
        *(float4*)(sB + row * 64 + c4) = *(const float4*)(Bm + row * 512 + c4);
    }
    __syncthreads();

    const int r  = t >> 1;
    const int s0 = (t & 1) * 32;
    float acc[32];
#pragma unroll
    for (int i = 0; i < 32; ++i) acc[i] = 0.f;
#pragma unroll 4
    for (int k = 0; k < 64; ++k) {
        const float a = sA[r * 64 + k];
#pragma unroll
        for (int i = 0; i < 32; ++i) acc[i] = fmaf(a, sB[k * 64 + s0 + i], acc[i]);
    }
    const int q = r >> 1, pr = r & 1;
#pragma unroll
    for (int i = 0; i < 32; ++i) {
        const int j = s0 + i;
        g_w2[((size_t)(combo * 32 + q) * 32 + (j >> 1)) * 4 + (j & 1) * 2 + pr] = acc[i];
    }
}

// ---------------- pass 0: core0 -> g_vA[rank1] ----------------
__global__ __launch_bounds__(TILE, 3) void k_pass0(const float* __restrict__ core0)
{
    __shared__ float vt[TILE * VS];
    __shared__ int   opos[TILE];
    __shared__ int   keys[TILE];
    const int t = threadIdx.x, lane = t & 31, w = t >> 5;
    const int base = blockIdx.x * TILE;

    {
        const int sid = g_perm[0][base + t];
        const unsigned dg = g_dig[sid];
        keys[t] = pair_key(dg, 0);
        opos[t] = g_rk1[sid];
        // v0 = core0[d0]: 8 distinct rows, L1-resident; thread fills own row
        const float4* src = (const float4*)(core0 + (dg & 7u) * RANK);
        float* drow = vt + t * VS;
#pragma unroll
        for (int j = 0; j < 16; ++j) *(float4*)(drow + 4 * j) = src[j];
    }
    __syncthreads();

    u64 wa[32], wb[32];
    int cur = -1;
#pragma unroll 1
    for (int s = w * 32; s < w * 32 + 32; ++s) {
        const int key = keys[s];
        if (key != cur) {
            cur = key;
            const ulonglong2* wp = (const ulonglong2*)g_w2 + (size_t)key * 1024 + lane;
#pragma unroll
            for (int k = 0; k < 32; ++k) {
                const ulonglong2 z = wp[k * 32];   // coalesced LDG.128
                wa[k] = z.x; wb[k] = z.y;
            }
        }
        const ulonglong2* vr = (const ulonglong2*)(vt + s * VS);
        u64 a0 = 0ull, a1 = 0ull, b0 = 0ull, b1 = 0ull;
#pragma unroll
        for (int q = 0; q < 16; ++q) {
            const ulonglong2 p = vr[q];            // uniform LDS.128 (broadcast)
            a0 = ffma2(wa[2 * q + 0], p.x, a0);
            b0 = ffma2(wb[2 * q + 0], p.x, b0);
            a1 = ffma2(wa[2 * q + 1], p.y, a1);
            b1 = ffma2(wb[2 * q + 1], p.y, b1);
        }
        float x0, x1, y0, y1;
        upk2(add2(a0, a1), x0, x1);
        upk2(add2(b0, b1), y0, y1);
        *(u64*)(g_vA + (size_t)opos[s] * 64 + 2 * lane) = pk2(x0 + x1, y0 + y1);
    }
}

// ---------------- passes 1,2: sequential gather -> placed scatter ----------
// pass==1: vin=g_vA, vout=g_vB, out position = g_rk2[sid]
// pass==2: vin=g_vB, vout=g_vA, out position = sid (natural order for epi)
__global__ __launch_bounds__(TILE, 3) void k_passSeq(int pass,
                                                     const float* __restrict__ vin,
                                                     float* __restrict__ vout)
{
    __shared__ float vt[TILE * VS];
    __shared__ int   opos[TILE];
    __shared__ int   keys[TILE];
    const int t = threadIdx.x, lane = t & 31, w = t >> 5;
    const int base = blockIdx.x * TILE;

    {
        const int sid = g_perm[pass][base + t];
        keys[t] = pair_key(g_dig[sid], pass);
        opos[t] = (pass == 1) ? g_rk2[sid] : sid;
    }
    // sequential coalesced gather: tile row r lives at vin[base + r]
    {
        const int h = t & 1;
#pragma unroll
        for (int r = t >> 1; r < TILE; r += 64) {
            const float* srow = vin + (size_t)(base + r) * 64;
            float* drow = vt + r * VS;
#pragma unroll
            for (int j = 0; j < 8; ++j) {
                const int c = 2 * j + h;
                *(float4*)(drow + c * 4) = *(const float4*)(srow + c * 4);
            }
        }
    }
    __syncthreads();

    u64 wa[32], wb[32];
    int cur = -1;
#pragma unroll 1
    for (int s = w * 32; s < w * 32 + 32; ++s) {
        const int key = keys[s];
        if (key != cur) {
            cur = key;
            const ulonglong2* wp = (const ulonglong2*)g_w2
                                   + (size_t)(pass * 64 + key) * 1024 + lane;
#pragma unroll
            for (int k = 0; k < 32; ++k) {
                const ulonglong2 z = wp[k * 32];
                wa[k] = z.x; wb[k] = z.y;
            }
        }
        const ulonglong2* vr = (const ulonglong2*)(vt + s * VS);
        u64 a0 = 0ull, a1 = 0ull, b0 = 0ull, b1 = 0ull;
#pragma unroll
        for (int q = 0; q < 16; ++q) {
            const ulonglong2 p = vr[q];
            a0 = ffma2(wa[2 * q + 0], p.x, a0);
            b0 = ffma2(wb[2 * q + 0], p.x, b0);
            a1 = ffma2(wa[2 * q + 1], p.y, a1);
            b1 = ffma2(wb[2 * q + 1], p.y, b1);
        }
        float x0, x1, y0, y1;
        upk2(add2(a0, a1), x0, x1);
        upk2(add2(b0, b1), y0, y1);
        *(u64*)(vout + (size_t)opos[s] * 64 + 2 * lane) = pk2(x0 + x1, y0 + y1);
    }
}

// ---------------- epilogue: fold W7(d7) @ (payload @ SH) ----------------
__global__ __launch_bounds__(256) void k_epi(const float* __restrict__ coords,
                                             const float* __restrict__ viewdirs,
                                             const float* __restrict__ cores,
                                             const float* __restrict__ payload,
                                             float* __restrict__ out, int N)
{
    __shared__ float pp[256];        // P' : 64 x float4
    __shared__ float wps[8 * 260];   // WP[d][r][j]: d*260 + r*4 + j
    const int tid = threadIdx.x;
    const int b   = blockIdx.x;
    const int n   = b * 256 + tid;

    const float cx = coords[3 * n + 0];
    const float cy = coords[3 * n + 1];
    const float cz = coords[3 * n + 2];
    const float msk = (fabsf(cx) <= 1.f && fabsf(cy) <= 1.f && fabsf(cz) <= 1.f) ? 1.f : 0.f;
    const int d7 = (int)((g_dig[n] >> 28) & 7u);

    if (tid < RANK) {
        const float* vd = viewdirs + 3 * b;
        const float dx = vd[0], dy = vd[1], dz = vd[2];
        float shv[9];
        shv[0] = 0.28209479177387814f;
        shv[1] = -0.4886025119029199f * dy;
        shv[2] =  0.4886025119029199f * dz;
        shv[3] = -0.4886025119029199f * dx;
        shv[4] =  1.0925484305920792f * dx * dy;
        shv[5] = -1.0925484305920792f * dy * dz;
        shv[6] =  0.31539156525252005f * (2.f * dz * dz - dx * dx - dy * dy);
        shv[7] = -1.0925484305920792f * dx * dz;
        shv[8] =  0.5462742152960396f * (dx * dx - dy * dy);
        const float* pr = payload + tid * 28;
        float s0 = 0.f, s1 = 0.f, s2 = 0.f;
#pragma unroll
        for (int j = 0; j < 9; ++j) {
            s0 = fmaf(pr[j],      shv[j], s0);
            s1 = fmaf(pr[9 + j],  shv[j], s1);
            s2 = fmaf(pr[18 + j], shv[j], s2);
        }
        *(float4*)(pp + 4 * tid) = make_float4(s0, s1, s2, pr[27]);
    }
    __syncthreads();

    // WP[d] = W7(d) @ P'
#pragma unroll
    for (int i = 0; i < 2; ++i) {
        const int idx = tid + i * 256;
        const int d = idx >> 6, r = idx & 63;
        const float* src = cores + (size_t)6 * 32768 + r * 512 + d * 64;
        float a0 = 0.f, a1 = 0.f, a2 = 0.f, a3 = 0.f;
#pragma unroll 4
        for (int s4 = 0; s4 < 16; ++s4) {
            const float4 w4 = *(const float4*)(src + 4 * s4);
            const float4 p0 = *(const float4*)(pp + 4 * (4 * s4 + 0));
            const float4 p1 = *(const float4*)(pp + 4 * (4 * s4 + 1));
            const float4 p2 = *(const float4*)(pp + 4 * (4 * s4 + 2));
            const float4 p3 = *(const float4*)(pp + 4 * (4 * s4 + 3));
            a0 = fmaf(w4.x, p0.x, a0); a1 = fmaf(w4.x, p0.y, a1);
            a2 = fmaf(w4.x, p0.z, a2); a3 = fmaf(w4.x, p0.w, a3);
            a0 = fmaf(w4.y, p1.x, a0); a1 = fmaf(w4.y, p1.y, a1);
            a2 = fmaf(w4.y, p1.z, a2); a3 = fmaf(w4.y, p1.w, a3);
            a0 = fmaf(w4.z, p2.x, a0); a1 = fmaf(w4.z, p2.y, a1);
            a2 = fmaf(w4.z, p2.z, a2); a3 = fmaf(w4.z, p2.w, a3);
            a0 = fmaf(w4.w, p3.x, a0); a1 = fmaf(w4.w, p3.y, a1);
            a2 = fmaf(w4.w, p3.z, a2); a3 = fmaf(w4.w, p3.w, a3);
        }
        *(float4*)(wps + d * 260 + r * 4) = make_float4(a0, a1, a2, a3);
    }
    __syncthreads();

    // out = v6 @ WP[d7]  (v6 rows in g_vA, natural order -> coalesced)
    float o0 = 0.f, o1 = 0.f, o2 = 0.f, o3 = 0.f;
    {
        const float* vrowg = g_vA + (size_t)n * 64;
        const float* wrow = wps + d7 * 260;
#pragma unroll
        for (int q = 0; q < 16; ++q) {
            const float4 t = *(const float4*)(vrowg + 4 * q);
            const float4 p0 = *(const float4*)(wrow + 4 * (4 * q + 0));
            const float4 p1 = *(const float4*)(wrow + 4 * (4 * q + 1));
            const float4 p2 = *(const float4*)(wrow + 4 * (4 * q + 2));
            const float4 p3 = *(const float4*)(wrow + 4 * (4 * q + 3));
            o0 = fmaf(t.x, p0.x, o0); o1 = fmaf(t.x, p0.y, o1);
            o2 = fmaf(t.x, p0.z, o2); o3 = fmaf(t.x, p0.w, o3);
            o0 = fmaf(t.y, p1.x, o0); o1 = fmaf(t.y, p1.y, o1);
            o2 = fmaf(t.y, p1.z, o2); o3 = fmaf(t.y, p1.w, o3);
            o0 = fmaf(t.z, p2.x, o0); o1 = fmaf(t.z, p2.y, o1);
            o2 = fmaf(t.z, p2.z, o2); o3 = fmaf(t.z, p2.w, o3);
            o0 = fmaf(t.w, p3.x, o0); o1 = fmaf(t.w, p3.y, o1);
            o2 = fmaf(t.w, p3.z, o2); o3 = fmaf(t.w, p3.w, o3);
        }
    }
    out[3 * n + 0] = o0 * msk;
    out[3 * n + 1] = o1 * msk;
    out[3 * n + 2] = o2 * msk;
    out[3 * N + n] = o3 * msk;   // sigma block after rgb block
}

extern "C" void kernel_launch(void* const* d_in, const int* in_sizes, int n_in,
                              void* d_out, int out_size) {
    const float* coords   = (const float*)d_in[0];  // (B,R,3)
    const float* viewdirs = (const float*)d_in[1];  // (B,3)
    const float* core0    = (const float*)d_in[2];  // (1,8,64)
    const float* cores    = (const float*)d_in[3];  // (7,64,8,64)
    const float* payload  = (const float*)d_in[4];  // (64,28)

    const int N = in_sizes[0] / 3;   // 262144
    const int B = in_sizes[1] / 3;   // 1024

    float* vA = nullptr; float* vB = nullptr;
    cudaGetSymbolAddress((void**)&vA, g_vA);
    cudaGetSymbolAddress((void**)&vB, g_vB);

    k_zero<<<1, 192>>>();
    k_keys<<<N / 256, 256>>>(coords);
    k_scan<<<1, 192>>>();
    precombine_kernel<<<192, 128>>>(cores);
    k_scatter<<<N / 256, 256>>>();
    k_pass0<<<N / TILE, TILE>>>(core0);
    k_passSeq<<<N / TILE, TILE>>>(1, vA, vB);
    k_passSeq<<<N / TILE, TILE>>>(2, vB, vA);
    k_epi<<<B, 256>>>(coords, viewdirs, cores, payload, (float*)d_out, N);
}